// round 5
// baseline (speedup 1.0000x reference)
#include <cuda_runtime.h>

#define BB    64
#define L1S   199
#define LL    200
#define NUMC  1000
#define DD    64
#define MM    50
#define DR    32          // d-range per scan block (d-split = 2)

// ---- scratch (static device globals; no allocation) ----
__device__ float g_Wall[NUMC*MM];      // softmax(kemb @ Mk^T)        [1000,50]
__device__ float g_Eall[2*NUMC*DD];    // sigmoid(vemb @ We + be)     [2000,64]
__device__ float g_Aall[2*NUMC*DD];    // tanh(vemb @ Wa + ba)        [2000,64]
__device__ float g_Kf  [NUMC*DD];      // kemb @ Wf[D:2D] + bf        [1000,64]
__device__ float g_read[BB*LL*DD];     // weighted read               [B,L,64]

// ---- fast transcendentals (MUFU-based, err ~1e-7 rel) ----
__device__ __forceinline__ float fast_sigmoid(float x) {
    return __fdividef(1.f, 1.f + __expf(-x));
}
__device__ __forceinline__ float fast_tanh(float x) {
    return 1.f - __fdividef(2.f, __expf(2.f * x) + 1.f);
}

// ---- packed f32x2 ops (Blackwell FFMA2; fma pipe, rt same as FFMA) ----
#define FMA2(d, a, b, c) \
    asm("fma.rn.f32x2 %0, %1, %2, %3;" : "=l"(d) : "l"(a), "l"(b), "l"(c))
#define PACK2(d, lo, hi) \
    asm("mov.b64 %0, {%1, %2};" : "=l"(d) : "f"(lo), "f"(hi))
#define UNPACK2(lo, hi, s) \
    asm("mov.b64 {%0, %1}, %2;" : "=f"(lo), "=f"(hi) : "l"(s))

// ============================================================
// Kernel V: vocab precompute. grid=250, block=256.
// Block stages We/Wa/Wf_bot/Mk^T in smem, computes 8 x-rows
// (E/A gates) + 4 k-rows (softmax W + Kf).
// ============================================================
__global__ __launch_bounds__(256) void vocab_kernel(
    const float* __restrict__ kemb,  const float* __restrict__ vemb,
    const float* __restrict__ Mk,
    const float* __restrict__ We,    const float* __restrict__ be,
    const float* __restrict__ Wa,    const float* __restrict__ ba,
    const float* __restrict__ Wf,    const float* __restrict__ bf)
{
    extern __shared__ float sm[];
    float* sWe  = sm;                 // 4096
    float* sWa  = sWe + DD*DD;        // 4096
    float* sWf  = sWa + DD*DD;        // 4096 (bottom half of Wf)
    float* sMkT = sWf + DD*DD;        // 3200, MkT[i*MM+m]=Mk[m*DD+i]
    float* vs   = sMkT + DD*MM;       // 8*64
    float* ks   = vs + 8*DD;          // 4*64
    float* part = ks + 4*DD;          // 4 pg * 2

    const int tid   = threadIdx.x;
    const int d     = tid & 63;
    const int pg    = tid >> 6;       // 0..3
    const int xbase = blockIdx.x * 8;
    const int kbase = blockIdx.x * 4;

    #pragma unroll
    for (int j = tid; j < DD*DD; j += 256) {
        sWe[j] = We[j];
        sWa[j] = Wa[j];
        sWf[j] = Wf[DD*DD + j];
    }
    #pragma unroll
    for (int j = tid; j < MM*DD; j += 256) {
        int m = j >> 6, i = j & 63;
        sMkT[i*MM + m] = Mk[j];
    }
    #pragma unroll
    for (int j = tid; j < 8*DD; j += 256)
        vs[j] = vemb[xbase*DD + j];
    if (tid < 4*DD)
        ks[tid] = kemb[kbase*DD + tid];
    __syncthreads();

    // ---- 8 x-rows: E/A gates (2 rows per pg) ----
    {
        const float bev = be[d], bav = ba[d];
        float ed0 = bev, ed1 = bev, ad0 = bav, ad1 = bav;
        const float* v0 = vs + (pg*2 + 0)*DD;
        const float* v1 = vs + (pg*2 + 1)*DD;
        #pragma unroll 8
        for (int i = 0; i < DD; i++) {
            const float we = sWe[i*DD + d];
            const float wa = sWa[i*DD + d];
            const float a0 = v0[i], a1 = v1[i];
            ed0 = fmaf(a0, we, ed0);  ad0 = fmaf(a0, wa, ad0);
            ed1 = fmaf(a1, we, ed1);  ad1 = fmaf(a1, wa, ad1);
        }
        int r0 = xbase + pg*2, r1 = r0 + 1;
        g_Eall[r0*DD + d] = fast_sigmoid(ed0);
        g_Aall[r0*DD + d] = fast_tanh(ad0);
        g_Eall[r1*DD + d] = fast_sigmoid(ed1);
        g_Aall[r1*DD + d] = fast_tanh(ad1);
    }

    // ---- 4 k-rows: Kf + softmax weights (1 row per pg) ----
    {
        float kf = bf[d];
        float lg = 0.f;
        const int md = (d < MM) ? d : 0;
        const float* k0 = ks + pg*DD;
        #pragma unroll 8
        for (int i = 0; i < DD; i++) {
            const float a0 = k0[i];
            kf = fmaf(a0, sWf[i*DD + d], kf);
            lg = fmaf(a0, sMkT[i*MM + md], lg);
        }
        g_Kf[(kbase + pg)*DD + d] = kf;
        float lgv = (d < MM) ? __expf(lg) : 0.f;
        float ps = lgv;
        #pragma unroll
        for (int o = 16; o > 0; o >>= 1)
            ps += __shfl_xor_sync(0xffffffffu, ps, o);
        if ((d & 31) == 0) part[pg*2 + (d >> 5)] = ps;
        __syncthreads();
        if (d < MM)
            g_Wall[(kbase + pg)*MM + d] =
                __fdividef(lgv, part[pg*2] + part[pg*2 + 1]);
    }
}

// ============================================================
// Kernel S: sequential memory scan, FFMA2-packed inner loop.
// grid = 128 (b = blk>>1, d-half = blk&1), block = 256.
// tid = dl*8 + g : warp = 4 d-lanes x 8 m-groups -> read-
// reduction over g is 3 shfl_xor. mv in 3 f32x2 pairs + tail.
// ============================================================
__global__ __launch_bounds__(256) void scan_kernel(
    const int*  __restrict__ cseqs,  const int* __restrict__ rseqs,
    const int*  __restrict__ shc,    const int* __restrict__ shr,
    const float* __restrict__ Mv0)
{
    extern __shared__ float smem[];
    float* sw = smem;                    // LL*MM = 10000
    float* se = sw + LL*MM;              // LL*DR = 6400
    float* sa = se + LL*DR;              // LL*DR = 6400
    int*   sq = (int*)(sa + LL*DR);      // LL
    int*   sx = sq + LL;                 // LL

    const int b     = blockIdx.x >> 1;
    const int dbase = (blockIdx.x & 1) * DR;
    const int tid   = threadIdx.x;

    if (tid < LL) {
        int t = tid;
        int q  = (t == 0) ? cseqs[b*L1S] : shc[b*L1S + t - 1];
        int rr = (t == 0) ? rseqs[b*L1S] : shr[b*L1S + t - 1];
        sq[t] = q;
        sx[t] = q + NUMC * rr;
    }
    __syncthreads();

    for (int j = tid; j < LL*MM; j += 256) {
        int t = j / MM, m = j - t*MM;
        sw[j] = g_Wall[sq[t]*MM + m];
    }
    for (int j = tid; j < LL*DR; j += 256) {
        int t = j >> 5, dl = j & (DR-1);
        int off = sx[t]*DD + dbase + dl;
        se[j] = g_Eall[off];
        sa[j] = g_Aall[off];
    }

    const int g  = tid & 7;
    const int dl = tid >> 3;

    // mv pairs: mvp[pi] = (Mv[g+16pi], Mv[g+16pi+8]) at column dbase+dl
    unsigned long long mvp[3];
    #pragma unroll
    for (int pi = 0; pi < 3; pi++) {
        float m0 = Mv0[(g + 16*pi    )*DD + dbase + dl];
        float m1 = Mv0[(g + 16*pi + 8)*DD + dbase + dl];
        PACK2(mvp[pi], m0, m1);
    }
    float mv6 = (g < 2) ? Mv0[(g + 48)*DD + dbase + dl] : 0.f;
    __syncthreads();

    float* outr = g_read + b*LL*DD + dbase + dl;
    const float fz = 0.f;

    for (int t = 0; t < LL; t++) {
        const float e  = se[t*DR + dl];
        const float a  = sa[t*DR + dl];
        const float ne = -e;
        const float* wt = sw + t*MM;

        unsigned long long nep, aap, prp;
        PACK2(nep, ne, ne);
        PACK2(aap, a, a);
        PACK2(prp, fz, fz);

        #pragma unroll
        for (int pi = 0; pi < 3; pi++) {
            float w0 = wt[g + 16*pi];
            float w1 = wt[g + 16*pi + 8];
            unsigned long long wp, tt;
            PACK2(wp, w0, w1);
            FMA2(prp, wp, mvp[pi], prp);        // pr += w * mv (read first)
            FMA2(tt, nep, mvp[pi], aap);        // t = a - e*mv
            FMA2(mvp[pi], wp, tt, mvp[pi]);     // mv += w * t
        }
        float pr6 = 0.f;
        if (g < 2) {
            float wm = wt[g + 48];
            pr6 = wm * mv6;
            mv6 = fmaf(wm, fmaf(ne, mv6, a), mv6);
        }
        float plo, phi;
        UNPACK2(plo, phi, prp);
        float pr = plo + phi + pr6;
        pr += __shfl_xor_sync(0xffffffffu, pr, 1);
        pr += __shfl_xor_sync(0xffffffffu, pr, 2);
        pr += __shfl_xor_sync(0xffffffffu, pr, 4);
        if (g == 0) outr[t*DD] = pr;
    }
}

// ============================================================
// Kernel C: output MLP. 32 positions/block, grid=400, block=256.
// Warp w owns positions w*4..w*4+3; lane owns d-cols (lane, lane+32)
// -> one warp covers all 64 d, reduction is pure shfl.
// ============================================================
__global__ __launch_bounds__(256) void output_kernel(
    const int*  __restrict__ cseqs, const int* __restrict__ shc,
    const float* __restrict__ Wf,   const float* __restrict__ Wp,
    const float* __restrict__ bp,   float* __restrict__ out)
{
    __shared__ float sW[DD*DD];        // Wf top half [i][d]
    __shared__ float rs[32][DD];

    const int tid   = threadIdx.x;
    const int lane  = tid & 31;
    const int warp  = tid >> 5;        // 0..7
    const int pbase = blockIdx.x * 32;

    #pragma unroll
    for (int j = tid; j < DD*DD/4; j += 256)
        ((float4*)sW)[j] = ((const float4*)Wf)[j];
    #pragma unroll
    for (int j = tid; j < 32*DD/4; j += 256)
        ((float4*)rs)[j] = ((const float4*)(g_read + pbase*DD))[j];
    __syncthreads();

    float acc0[4], acc1[4];
    int posq[4];
    #pragma unroll
    for (int jj = 0; jj < 4; jj++) {
        int pos = pbase + warp*4 + jj;
        int bb = pos / LL, t = pos - bb*LL;
        int q = (t == 0) ? cseqs[bb*L1S] : shc[bb*L1S + t - 1];
        posq[jj] = pos;
        acc0[jj] = g_Kf[q*DD + lane];
        acc1[jj] = g_Kf[q*DD + 32 + lane];
    }

    const float4* r0 = (const float4*)rs[warp*4 + 0];
    const float4* r1 = (const float4*)rs[warp*4 + 1];
    const float4* r2 = (const float4*)rs[warp*4 + 2];
    const float4* r3 = (const float4*)rs[warp*4 + 3];

    #pragma unroll
    for (int i4 = 0; i4 < DD/4; i4++) {
        float ra[4], rb[4], rc[4], rd[4];
        *(float4*)ra = r0[i4];
        *(float4*)rb = r1[i4];
        *(float4*)rc = r2[i4];
        *(float4*)rd = r3[i4];
        #pragma unroll
        for (int k = 0; k < 4; k++) {
            const float wv0 = sW[(4*i4 + k)*DD + lane];
            const float wv1 = sW[(4*i4 + k)*DD + 32 + lane];
            acc0[0] = fmaf(ra[k], wv0, acc0[0]);
            acc1[0] = fmaf(ra[k], wv1, acc1[0]);
            acc0[1] = fmaf(rb[k], wv0, acc0[1]);
            acc1[1] = fmaf(rb[k], wv1, acc1[1]);
            acc0[2] = fmaf(rc[k], wv0, acc0[2]);
            acc1[2] = fmaf(rc[k], wv1, acc1[2]);
            acc0[3] = fmaf(rd[k], wv0, acc0[3]);
            acc1[3] = fmaf(rd[k], wv1, acc1[3]);
        }
    }

    const float wp0 = Wp[lane];
    const float wp1 = Wp[32 + lane];
    const float bpv = bp[0];
    #pragma unroll
    for (int jj = 0; jj < 4; jj++) {
        float p = fast_tanh(acc0[jj]) * wp0 + fast_tanh(acc1[jj]) * wp1;
        #pragma unroll
        for (int o = 16; o > 0; o >>= 1)
            p += __shfl_xor_sync(0xffffffffu, p, o);
        if (lane == 0)
            out[posq[jj]] = fast_sigmoid(p + bpv);
    }
}

// ============================================================
extern "C" void kernel_launch(void* const* d_in, const int* in_sizes, int n_in,
                              void* d_out, int out_size)
{
    const int*   cseqs = (const int*)  d_in[0];
    const int*   rseqs = (const int*)  d_in[1];
    const int*   shc   = (const int*)  d_in[2];
    const int*   shr   = (const int*)  d_in[3];
    const float* kemb  = (const float*)d_in[4];
    const float* vemb  = (const float*)d_in[5];
    const float* Mk    = (const float*)d_in[6];
    const float* Mv0   = (const float*)d_in[7];
    const float* Wf    = (const float*)d_in[8];
    const float* bf    = (const float*)d_in[9];
    const float* We    = (const float*)d_in[10];
    const float* be    = (const float*)d_in[11];
    const float* Wa    = (const float*)d_in[12];
    const float* ba    = (const float*)d_in[13];
    const float* Wp    = (const float*)d_in[14];
    const float* bp    = (const float*)d_in[15];
    float* out = (float*)d_out;

    size_t vsm = (size_t)(3*DD*DD + DD*MM + 8*DD + 4*DD + 8) * sizeof(float);
    cudaFuncSetAttribute(vocab_kernel,
                         cudaFuncAttributeMaxDynamicSharedMemorySize, (int)vsm);
    vocab_kernel<<<250, 256, vsm>>>(kemb, vemb, Mk, We, be, Wa, ba, Wf, bf);

    size_t ssm = (size_t)(LL*MM + 2*LL*DR) * sizeof(float) + 2*LL*sizeof(int);
    cudaFuncSetAttribute(scan_kernel,
                         cudaFuncAttributeMaxDynamicSharedMemorySize, (int)ssm);
    scan_kernel<<<BB*2, 256, ssm>>>(cseqs, rseqs, shc, shr, Mv0);

    output_kernel<<<BB*LL/32, 256>>>(cseqs, shc, Wf, Wp, bp, out);
}

// round 6
// speedup vs baseline: 1.0506x; 1.0506x over previous
#include <cuda_runtime.h>

#define BB    64
#define L1S   199
#define LL    200
#define NUMC  1000
#define DD    64
#define MM    50
#define DR    32          // d-range per scan block (d-split = 2)

// ---- scratch (static device globals; no allocation) ----
__device__ float g_Wall[NUMC*MM];      // softmax(kemb @ Mk^T)        [1000,50]
__device__ float g_Eall[2*NUMC*DD];    // sigmoid(vemb @ We + be)     [2000,64]
__device__ float g_Aall[2*NUMC*DD];    // tanh(vemb @ Wa + ba)        [2000,64]
__device__ float g_Kf  [NUMC*DD];      // kemb @ Wf[D:2D] + bf        [1000,64]
__device__ float g_read[BB*LL*DD];     // weighted read               [B,L,64]

// ---- fast transcendentals (MUFU-based, err ~1e-7 rel) ----
__device__ __forceinline__ float fast_sigmoid(float x) {
    return __fdividef(1.f, 1.f + __expf(-x));
}
__device__ __forceinline__ float fast_tanh(float x) {
    return 1.f - __fdividef(2.f, __expf(2.f * x) + 1.f);
}

// ---- packed f32x2 ops (Blackwell FFMA2, PTX-only) ----
#define FMA2(d, a, b, c) \
    asm("fma.rn.f32x2 %0, %1, %2, %3;" : "=l"(d) : "l"(a), "l"(b), "l"(c))
#define PACK2(d, lo, hi) \
    asm("mov.b64 %0, {%1, %2};" : "=l"(d) : "f"(lo), "f"(hi))
#define UNPACK2(lo, hi, s) \
    asm("mov.b64 {%0, %1}, %2;" : "=f"(lo), "=f"(hi) : "l"(s))

#define NEA 250   // EA blocks (8 x-rows each)
#define NWK 125   // WK blocks (8 k-rows each)

// ============================================================
// Kernel V: role-split vocab precompute. grid = 375, block = 256.
// Blocks [0,250): E/A gates for 8 x-rows (stage We+Wa, ~34KB smem).
// Blocks [250,375): softmax W + Kf for 8 k-rows (stage Wf_bot+Mk^T).
// ============================================================
__global__ __launch_bounds__(256) void vocab_kernel(
    const float* __restrict__ kemb,  const float* __restrict__ vemb,
    const float* __restrict__ Mk,
    const float* __restrict__ We,    const float* __restrict__ be,
    const float* __restrict__ Wa,    const float* __restrict__ ba,
    const float* __restrict__ Wf,    const float* __restrict__ bf)
{
    extern __shared__ float sm[];
    const int tid = threadIdx.x;
    const int d   = tid & 63;
    const int pg  = tid >> 6;         // 0..3

    if (blockIdx.x < NEA) {
        // ---------------- EA path: 8 x-rows ----------------
        float* sWe = sm;              // 4096
        float* sWa = sWe + DD*DD;     // 4096
        float* vs  = sWa + DD*DD;     // 8*64
        const int xbase = blockIdx.x * 8;

        #pragma unroll
        for (int j = tid; j < DD*DD; j += 256) {
            sWe[j] = We[j];
            sWa[j] = Wa[j];
        }
        #pragma unroll
        for (int j = tid; j < 8*DD; j += 256)
            vs[j] = vemb[xbase*DD + j];
        __syncthreads();

        const float bev = be[d], bav = ba[d];
        float ed0 = bev, ed1 = bev, ad0 = bav, ad1 = bav;
        const float* v0 = vs + (pg*2 + 0)*DD;
        const float* v1 = vs + (pg*2 + 1)*DD;
        #pragma unroll 8
        for (int i = 0; i < DD; i++) {
            const float we = sWe[i*DD + d];
            const float wa = sWa[i*DD + d];
            const float a0 = v0[i], a1 = v1[i];
            ed0 = fmaf(a0, we, ed0);  ad0 = fmaf(a0, wa, ad0);
            ed1 = fmaf(a1, we, ed1);  ad1 = fmaf(a1, wa, ad1);
        }
        int r0 = xbase + pg*2, r1 = r0 + 1;
        g_Eall[r0*DD + d] = fast_sigmoid(ed0);
        g_Aall[r0*DD + d] = fast_tanh(ad0);
        g_Eall[r1*DD + d] = fast_sigmoid(ed1);
        g_Aall[r1*DD + d] = fast_tanh(ad1);
    } else {
        // ---------------- WK path: 8 k-rows ----------------
        float* sWf  = sm;             // 4096 (Wf bottom half)
        float* sMkT = sWf + DD*DD;    // 3200, MkT[i*MM+m]=Mk[m*DD+i]
        float* ks   = sMkT + DD*MM;   // 8*64
        float* part = ks + 8*DD;      // 16
        const int kbase = (blockIdx.x - NEA) * 8;

        #pragma unroll
        for (int j = tid; j < DD*DD; j += 256)
            sWf[j] = Wf[DD*DD + j];
        #pragma unroll
        for (int j = tid; j < MM*DD; j += 256) {
            int m = j >> 6, i = j & 63;
            sMkT[i*MM + m] = Mk[j];
        }
        #pragma unroll
        for (int j = tid; j < 8*DD; j += 256)
            ks[j] = kemb[kbase*DD + j];
        __syncthreads();

        const float bfv = bf[d];
        float kf0 = bfv, kf1 = bfv;
        float lg0 = 0.f, lg1 = 0.f;
        const int md = (d < MM) ? d : 0;
        const float* k0 = ks + (pg*2 + 0)*DD;
        const float* k1 = ks + (pg*2 + 1)*DD;
        #pragma unroll 8
        for (int i = 0; i < DD; i++) {
            const float wf = sWf[i*DD + d];
            const float mk = sMkT[i*MM + md];
            const float a0 = k0[i], a1 = k1[i];
            kf0 = fmaf(a0, wf, kf0);  lg0 = fmaf(a0, mk, lg0);
            kf1 = fmaf(a1, wf, kf1);  lg1 = fmaf(a1, mk, lg1);
        }
        g_Kf[(kbase + pg*2 + 0)*DD + d] = kf0;
        g_Kf[(kbase + pg*2 + 1)*DD + d] = kf1;

        float lgv0 = (d < MM) ? __expf(lg0) : 0.f;
        float lgv1 = (d < MM) ? __expf(lg1) : 0.f;
        float ps0 = lgv0, ps1 = lgv1;
        #pragma unroll
        for (int o = 16; o > 0; o >>= 1) {
            ps0 += __shfl_xor_sync(0xffffffffu, ps0, o);
            ps1 += __shfl_xor_sync(0xffffffffu, ps1, o);
        }
        if ((d & 31) == 0) {
            part[pg*4 + (d >> 5)]     = ps0;
            part[pg*4 + 2 + (d >> 5)] = ps1;
        }
        __syncthreads();
        if (d < MM) {
            g_Wall[(kbase + pg*2 + 0)*MM + d] =
                __fdividef(lgv0, part[pg*4] + part[pg*4 + 1]);
            g_Wall[(kbase + pg*2 + 1)*MM + d] =
                __fdividef(lgv1, part[pg*4 + 2] + part[pg*4 + 3]);
        }
    }
}

// ============================================================
// Kernel S: sequential memory scan, permuted-layout smem.
// grid = 128 (b = blk>>1, half = blk&1), block = 256.
// tid = dl*8 + g; warp = 4 d-lanes x 8 m-groups.
// sw permuted per t: [pi*16 + g*2 + j] = w[g + 16*pi + 8*j]
// so each thread does 3x LDS.64; (e,a) interleaved -> 1x LDS.64.
// ============================================================
__global__ __launch_bounds__(256) void scan_kernel(
    const int*  __restrict__ cseqs,  const int* __restrict__ rseqs,
    const int*  __restrict__ shc,    const int* __restrict__ shr,
    const float* __restrict__ Mv0)
{
    extern __shared__ float smem[];
    float* sw  = smem;                   // LL*64 = 12800 (permuted w)
    float* sea = sw + LL*64;             // LL*64 = 12800 (e,a pairs)
    int*   sq  = (int*)(sea + LL*64);    // LL
    int*   sx  = sq + LL;                // LL

    const int b     = blockIdx.x >> 1;
    const int dbase = (blockIdx.x & 1) * DR;
    const int tid   = threadIdx.x;

    if (tid < LL) {
        int t = tid;
        int q  = (t == 0) ? cseqs[b*L1S] : shc[b*L1S + t - 1];
        int rr = (t == 0) ? rseqs[b*L1S] : shr[b*L1S + t - 1];
        sq[t] = q;
        sx[t] = q + NUMC * rr;
    }
    __syncthreads();

    // stage w permuted
    for (int j = tid; j < LL*MM; j += 256) {
        int t = j / MM, m = j - t*MM;
        float wv = g_Wall[sq[t]*MM + m];
        int idx;
        if (m < 48) {
            int pi  = m >> 4;
            int rem = m & 15;
            idx = pi*16 + ((rem & 7) << 1) + (rem >> 3);
        } else {
            idx = m;       // 48, 49
        }
        sw[t*64 + idx] = wv;
    }
    // stage (e,a) interleaved
    for (int j = tid; j < LL*DR; j += 256) {
        int t = j >> 5, dl = j & (DR-1);
        int off = sx[t]*DD + dbase + dl;
        sea[t*64 + dl*2 + 0] = g_Eall[off];
        sea[t*64 + dl*2 + 1] = g_Aall[off];
    }

    const int g  = tid & 7;
    const int dl = tid >> 3;

    // mv pairs: mvp[pi] = (Mv[g+16pi], Mv[g+16pi+8]) at column dbase+dl
    unsigned long long mvp[3];
    #pragma unroll
    for (int pi = 0; pi < 3; pi++) {
        float m0 = Mv0[(g + 16*pi    )*DD + dbase + dl];
        float m1 = Mv0[(g + 16*pi + 8)*DD + dbase + dl];
        PACK2(mvp[pi], m0, m1);
    }
    float mv6 = (g < 2) ? Mv0[(g + 48)*DD + dbase + dl] : 0.f;
    __syncthreads();

    float* outr = g_read + b*LL*DD + dbase + dl;
    const float fz = 0.f;
    const float2* swp  = (const float2*)sw;    // 32 pairs per t
    const float2* seap = (const float2*)sea;

    #pragma unroll 2
    for (int t = 0; t < LL; t++) {
        const float2 ea = seap[t*32 + dl];     // (e, a)
        const float ne = -ea.x;
        const float a  =  ea.y;

        unsigned long long nep, aap, prp;
        PACK2(nep, ne, ne);
        PACK2(aap, a, a);
        PACK2(prp, fz, fz);

        float2 w0 = swp[t*32 +      g];        // pi=0 pair
        float2 w1 = swp[t*32 +  8 + g];        // pi=1 pair
        float2 w2 = swp[t*32 + 16 + g];        // pi=2 pair

        unsigned long long wp, tt;
        PACK2(wp, w0.x, w0.y);
        FMA2(prp, wp, mvp[0], prp);
        FMA2(tt, nep, mvp[0], aap);
        FMA2(mvp[0], wp, tt, mvp[0]);

        PACK2(wp, w1.x, w1.y);
        FMA2(prp, wp, mvp[1], prp);
        FMA2(tt, nep, mvp[1], aap);
        FMA2(mvp[1], wp, tt, mvp[1]);

        PACK2(wp, w2.x, w2.y);
        FMA2(prp, wp, mvp[2], prp);
        FMA2(tt, nep, mvp[2], aap);
        FMA2(mvp[2], wp, tt, mvp[2]);

        float pr6 = 0.f;
        if (g < 2) {
            float wm = sw[t*64 + 48 + g];
            pr6 = wm * mv6;
            mv6 = fmaf(wm, fmaf(ne, mv6, a), mv6);
        }
        float plo, phi;
        UNPACK2(plo, phi, prp);
        float pr = plo + phi + pr6;
        pr += __shfl_xor_sync(0xffffffffu, pr, 1);
        pr += __shfl_xor_sync(0xffffffffu, pr, 2);
        pr += __shfl_xor_sync(0xffffffffu, pr, 4);
        if (g == 0) outr[t*DD] = pr;
    }
}

// ============================================================
// Kernel C: output MLP. 32 positions/block, grid=400, block=256.
// Warp w owns positions w*4..w*4+3; lane owns d-cols (lane, lane+32).
// ============================================================
__global__ __launch_bounds__(256) void output_kernel(
    const int*  __restrict__ cseqs, const int* __restrict__ shc,
    const float* __restrict__ Wf,   const float* __restrict__ Wp,
    const float* __restrict__ bp,   float* __restrict__ out)
{
    __shared__ float sW[DD*DD];        // Wf top half [i][d]
    __shared__ float rs[32][DD];

    const int tid   = threadIdx.x;
    const int lane  = tid & 31;
    const int warp  = tid >> 5;        // 0..7
    const int pbase = blockIdx.x * 32;

    #pragma unroll
    for (int j = tid; j < DD*DD/4; j += 256)
        ((float4*)sW)[j] = ((const float4*)Wf)[j];
    #pragma unroll
    for (int j = tid; j < 32*DD/4; j += 256)
        ((float4*)rs)[j] = ((const float4*)(g_read + pbase*DD))[j];
    __syncthreads();

    float acc0[4], acc1[4];
    int posq[4];
    #pragma unroll
    for (int jj = 0; jj < 4; jj++) {
        int pos = pbase + warp*4 + jj;
        int bb = pos / LL, t = pos - bb*LL;
        int q = (t == 0) ? cseqs[bb*L1S] : shc[bb*L1S + t - 1];
        posq[jj] = pos;
        acc0[jj] = g_Kf[q*DD + lane];
        acc1[jj] = g_Kf[q*DD + 32 + lane];
    }

    const float4* r0 = (const float4*)rs[warp*4 + 0];
    const float4* r1 = (const float4*)rs[warp*4 + 1];
    const float4* r2 = (const float4*)rs[warp*4 + 2];
    const float4* r3 = (const float4*)rs[warp*4 + 3];

    #pragma unroll
    for (int i4 = 0; i4 < DD/4; i4++) {
        float ra[4], rb[4], rc[4], rd[4];
        *(float4*)ra = r0[i4];
        *(float4*)rb = r1[i4];
        *(float4*)rc = r2[i4];
        *(float4*)rd = r3[i4];
        #pragma unroll
        for (int k = 0; k < 4; k++) {
            const float wv0 = sW[(4*i4 + k)*DD + lane];
            const float wv1 = sW[(4*i4 + k)*DD + 32 + lane];
            acc0[0] = fmaf(ra[k], wv0, acc0[0]);
            acc1[0] = fmaf(ra[k], wv1, acc1[0]);
            acc0[1] = fmaf(rb[k], wv0, acc0[1]);
            acc1[1] = fmaf(rb[k], wv1, acc1[1]);
            acc0[2] = fmaf(rc[k], wv0, acc0[2]);
            acc1[2] = fmaf(rc[k], wv1, acc1[2]);
            acc0[3] = fmaf(rd[k], wv0, acc0[3]);
            acc1[3] = fmaf(rd[k], wv1, acc1[3]);
        }
    }

    const float wp0 = Wp[lane];
    const float wp1 = Wp[32 + lane];
    const float bpv = bp[0];
    #pragma unroll
    for (int jj = 0; jj < 4; jj++) {
        float p = fast_tanh(acc0[jj]) * wp0 + fast_tanh(acc1[jj]) * wp1;
        #pragma unroll
        for (int o = 16; o > 0; o >>= 1)
            p += __shfl_xor_sync(0xffffffffu, p, o);
        if (lane == 0)
            out[posq[jj]] = fast_sigmoid(p + bpv);
    }
}

// ============================================================
extern "C" void kernel_launch(void* const* d_in, const int* in_sizes, int n_in,
                              void* d_out, int out_size)
{
    const int*   cseqs = (const int*)  d_in[0];
    const int*   rseqs = (const int*)  d_in[1];
    const int*   shc   = (const int*)  d_in[2];
    const int*   shr   = (const int*)  d_in[3];
    const float* kemb  = (const float*)d_in[4];
    const float* vemb  = (const float*)d_in[5];
    const float* Mk    = (const float*)d_in[6];
    const float* Mv0   = (const float*)d_in[7];
    const float* Wf    = (const float*)d_in[8];
    const float* bf    = (const float*)d_in[9];
    const float* We    = (const float*)d_in[10];
    const float* be    = (const float*)d_in[11];
    const float* Wa    = (const float*)d_in[12];
    const float* ba    = (const float*)d_in[13];
    const float* Wp    = (const float*)d_in[14];
    const float* bp    = (const float*)d_in[15];
    float* out = (float*)d_out;

    size_t vsm = (size_t)(2*DD*DD + 8*DD + 32) * sizeof(float);  // EA >= WK
    cudaFuncSetAttribute(vocab_kernel,
                         cudaFuncAttributeMaxDynamicSharedMemorySize, (int)vsm);
    vocab_kernel<<<NEA + NWK, 256, vsm>>>(kemb, vemb, Mk, We, be, Wa, ba, Wf, bf);

    size_t ssm = (size_t)(2*LL*64) * sizeof(float) + 2*LL*sizeof(int);
    cudaFuncSetAttribute(scan_kernel,
                         cudaFuncAttributeMaxDynamicSharedMemorySize, (int)ssm);
    scan_kernel<<<BB*2, 256, ssm>>>(cseqs, rseqs, shc, shr, Mv0);

    output_kernel<<<BB*LL/32, 256>>>(cseqs, shc, Wf, Wp, bp, out);
}

// round 7
// speedup vs baseline: 1.0928x; 1.0402x over previous
#include <cuda_runtime.h>

#define BB    64
#define L1S   199
#define LL    200
#define NUMC  1000
#define DD    64
#define MM    50
#define DR    32          // d-range per scan block (d-split = 2)
#define CC    4           // time chunks
#define CT    50          // steps per chunk (LL/CC)
#define NBLK  (BB*CC*2)   // 512 phase blocks

// ---- scratch (static device globals; no allocation) ----
__device__ float  g_Wall[NUMC*64];     // softmax, padded to 64 (zeros 50..63)
__device__ float  g_Eall[2*NUMC*DD];   // sigmoid(vemb @ We + be)
__device__ float  g_Aall[2*NUMC*DD];   // tanh(vemb @ Wa + ba)
__device__ float  g_Kf  [NUMC*DD];     // kemb @ Wf[D:2D] + bf
__device__ float  g_read[BB*LL*DD];    // weighted read
__device__ float2 gA[NBLK*4*256];      // chunk affine scale  (per pair,thread)
__device__ float2 gB[NBLK*4*256];      // chunk affine offset

// ---- fast transcendentals ----
__device__ __forceinline__ float fast_sigmoid(float x) {
    return __fdividef(1.f, 1.f + __expf(-x));
}
__device__ __forceinline__ float fast_tanh(float x) {
    return 1.f - __fdividef(2.f, __expf(2.f * x) + 1.f);
}

// ---- packed f32x2 ops ----
#define FMA2(d, a, b, c) \
    asm("fma.rn.f32x2 %0, %1, %2, %3;" : "=l"(d) : "l"(a), "l"(b), "l"(c))
#define MUL2(d, a, b) \
    asm("mul.rn.f32x2 %0, %1, %2;" : "=l"(d) : "l"(a), "l"(b))
#define PACK2(d, lo, hi) \
    asm("mov.b64 %0, {%1, %2};" : "=l"(d) : "f"(lo), "f"(hi))
#define UNPACK2(lo, hi, s) \
    asm("mov.b64 {%0, %1}, %2;" : "=f"(lo), "=f"(hi) : "l"(s))

#define NEA 250
#define NWK 125

// ============================================================
// Kernel V: role-split vocab precompute (float4 staging).
// ============================================================
__global__ __launch_bounds__(256) void vocab_kernel(
    const float* __restrict__ kemb,  const float* __restrict__ vemb,
    const float* __restrict__ Mk,
    const float* __restrict__ We,    const float* __restrict__ be,
    const float* __restrict__ Wa,    const float* __restrict__ ba,
    const float* __restrict__ Wf,    const float* __restrict__ bf)
{
    extern __shared__ float sm[];
    const int tid = threadIdx.x;
    const int d   = tid & 63;
    const int pg  = tid >> 6;

    if (blockIdx.x < NEA) {
        float* sWe = sm;
        float* sWa = sWe + DD*DD;
        float* vs  = sWa + DD*DD;
        const int xbase = blockIdx.x * 8;

        #pragma unroll
        for (int j = tid; j < DD*DD/4; j += 256) {
            ((float4*)sWe)[j] = ((const float4*)We)[j];
            ((float4*)sWa)[j] = ((const float4*)Wa)[j];
        }
        #pragma unroll
        for (int j = tid; j < 8*DD/4; j += 256)
            ((float4*)vs)[j] = ((const float4*)(vemb + xbase*DD))[j];
        __syncthreads();

        const float bev = be[d], bav = ba[d];
        float ed0 = bev, ed1 = bev, ad0 = bav, ad1 = bav;
        const float* v0 = vs + (pg*2 + 0)*DD;
        const float* v1 = vs + (pg*2 + 1)*DD;
        #pragma unroll 8
        for (int i = 0; i < DD; i++) {
            const float we = sWe[i*DD + d];
            const float wa = sWa[i*DD + d];
            const float a0 = v0[i], a1 = v1[i];
            ed0 = fmaf(a0, we, ed0);  ad0 = fmaf(a0, wa, ad0);
            ed1 = fmaf(a1, we, ed1);  ad1 = fmaf(a1, wa, ad1);
        }
        int r0 = xbase + pg*2, r1 = r0 + 1;
        g_Eall[r0*DD + d] = fast_sigmoid(ed0);
        g_Aall[r0*DD + d] = fast_tanh(ad0);
        g_Eall[r1*DD + d] = fast_sigmoid(ed1);
        g_Aall[r1*DD + d] = fast_tanh(ad1);
    } else {
        float* sWf  = sm;
        float* sMkT = sWf + DD*DD;
        float* ks   = sMkT + DD*MM;
        float* part = ks + 8*DD;
        const int kbase = (blockIdx.x - NEA) * 8;

        #pragma unroll
        for (int j = tid; j < DD*DD/4; j += 256)
            ((float4*)sWf)[j] = ((const float4*)(Wf + DD*DD))[j];
        #pragma unroll
        for (int j = tid; j < MM*DD; j += 256) {
            int m = j >> 6, i = j & 63;
            sMkT[i*MM + m] = Mk[j];
        }
        #pragma unroll
        for (int j = tid; j < 8*DD/4; j += 256)
            ((float4*)ks)[j] = ((const float4*)(kemb + kbase*DD))[j];
        __syncthreads();

        const float bfv = bf[d];
        float kf0 = bfv, kf1 = bfv;
        float lg0 = 0.f, lg1 = 0.f;
        const int md = (d < MM) ? d : 0;
        const float* k0 = ks + (pg*2 + 0)*DD;
        const float* k1 = ks + (pg*2 + 1)*DD;
        #pragma unroll 8
        for (int i = 0; i < DD; i++) {
            const float wf = sWf[i*DD + d];
            const float mk = sMkT[i*MM + md];
            const float a0 = k0[i], a1 = k1[i];
            kf0 = fmaf(a0, wf, kf0);  lg0 = fmaf(a0, mk, lg0);
            kf1 = fmaf(a1, wf, kf1);  lg1 = fmaf(a1, mk, lg1);
        }
        g_Kf[(kbase + pg*2 + 0)*DD + d] = kf0;
        g_Kf[(kbase + pg*2 + 1)*DD + d] = kf1;

        float lgv0 = (d < MM) ? __expf(lg0) : 0.f;
        float lgv1 = (d < MM) ? __expf(lg1) : 0.f;
        float ps0 = lgv0, ps1 = lgv1;
        #pragma unroll
        for (int o = 16; o > 0; o >>= 1) {
            ps0 += __shfl_xor_sync(0xffffffffu, ps0, o);
            ps1 += __shfl_xor_sync(0xffffffffu, ps1, o);
        }
        if ((d & 31) == 0) {
            part[pg*4 + (d >> 5)]     = ps0;
            part[pg*4 + 2 + (d >> 5)] = ps1;
        }
        __syncthreads();
        // padded rows (stride 64): zeros for d >= 50
        g_Wall[(kbase + pg*2 + 0)*64 + d] =
            __fdividef(lgv0, part[pg*4] + part[pg*4 + 1]);
        g_Wall[(kbase + pg*2 + 1)*64 + d] =
            __fdividef(lgv1, part[pg*4 + 2] + part[pg*4 + 3]);
    }
}

// ---- shared staging helper for phase kernels (inlined) ----
// sw: CT*64 permuted padded w; sea: CT*64 interleaved (e,a) for DR d-lanes
__device__ __forceinline__ void stage_chunk(
    float* sw, float* sea, int* sq, int* sx,
    const int* cseqs, const int* rseqs, const int* shc, const int* shr,
    int b, int c, int dbase, int tid)
{
    if (tid < CT) {
        int t = c*CT + tid;
        int q  = (t == 0) ? cseqs[b*L1S] : shc[b*L1S + t - 1];
        int rr = (t == 0) ? rseqs[b*L1S] : shr[b*L1S + t - 1];
        sq[tid] = q;
        sx[tid] = q + NUMC * rr;
    }
    __syncthreads();

    // w: CT rows x 16 float4 (stride-64 padded rows), permuted scatter
    for (int j = tid; j < CT*16; j += 256) {
        int i = j >> 4, f4 = j & 15;
        float4 wv = *(const float4*)&g_Wall[sq[i]*64 + f4*4];
        const float* w = (const float*)&wv;
        #pragma unroll
        for (int k = 0; k < 4; k++) {
            int m = f4*4 + k;
            int idx = (m >> 4)*16 + ((m & 7) << 1) + ((m >> 3) & 1);
            sw[i*64 + idx] = w[k];
        }
    }
    // (e,a): CT rows x 8 float4 over the DR d-lanes, interleaved
    for (int j = tid; j < CT*8; j += 256) {
        int i = j >> 3, f4 = j & 7;
        int off = sx[i]*DD + dbase + f4*4;
        float4 ev = *(const float4*)&g_Eall[off];
        float4 av = *(const float4*)&g_Aall[off];
        const float* e = (const float*)&ev;
        const float* a = (const float*)&av;
        #pragma unroll
        for (int k = 0; k < 4; k++) {
            sea[i*64 + (f4*4 + k)*2 + 0] = e[k];
            sea[i*64 + (f4*4 + k)*2 + 1] = a[k];
        }
    }
    __syncthreads();
}

// ============================================================
// Phase 1: per-chunk affine composition (A,B). grid = 512.
// block = (b*CC + c)*2 + half, 256 threads (g=tid&7, dl=tid>>3).
// ============================================================
__global__ __launch_bounds__(256) void scan_phase1(
    const int* __restrict__ cseqs, const int* __restrict__ rseqs,
    const int* __restrict__ shc,   const int* __restrict__ shr)
{
    __shared__ float sw[CT*64];
    __shared__ float sea[CT*64];
    __shared__ int   sq[CT], sx[CT];

    const int bx    = blockIdx.x;
    const int b     = bx >> 3;
    const int c     = (bx >> 1) & 3;
    const int dbase = (bx & 1) * DR;
    const int tid   = threadIdx.x;

    stage_chunk(sw, sea, sq, sx, cseqs, rseqs, shc, shr, b, c, dbase, tid);

    const int g  = tid & 7;
    const int dl = tid >> 3;
    (void)g; (void)dl;

    const float f1 = 1.f, f0 = 0.f;
    unsigned long long onep, A[4], Bv[4];
    PACK2(onep, f1, f1);
    #pragma unroll
    for (int pi = 0; pi < 4; pi++) { A[pi] = onep; PACK2(Bv[pi], f0, f0); }

    const float2* swp  = (const float2*)sw;
    const float2* seap = (const float2*)sea;

    #pragma unroll 2
    for (int i = 0; i < CT; i++) {
        const float2 ea = seap[i*32 + (tid >> 3)];
        const float ne = -ea.x;
        unsigned long long nep, ap;
        PACK2(nep, ne, ne);
        PACK2(ap, ea.y, ea.y);
        #pragma unroll
        for (int pi = 0; pi < 4; pi++) {
            float2 w2 = swp[i*32 + pi*8 + (tid & 7)];
            unsigned long long wp, alpha, beta;
            PACK2(wp, w2.x, w2.y);
            FMA2(alpha, nep, wp, onep);      // alpha = 1 - e*w
            MUL2(beta, wp, ap);              // beta  = w*a
            MUL2(A[pi], A[pi], alpha);       // A *= alpha
            FMA2(Bv[pi], alpha, Bv[pi], beta); // B = alpha*B + beta
        }
    }

    #pragma unroll
    for (int pi = 0; pi < 4; pi++) {
        float lo, hi;
        UNPACK2(lo, hi, A[pi]);
        gA[(bx*4 + pi)*256 + tid] = make_float2(lo, hi);
        UNPACK2(lo, hi, Bv[pi]);
        gB[(bx*4 + pi)*256 + tid] = make_float2(lo, hi);
    }
}

// ============================================================
// Phase 3: compose chunk-start state, replay 50 steps, emit reads.
// grid = 512, 256 threads.
// ============================================================
__global__ __launch_bounds__(256) void scan_phase3(
    const int* __restrict__ cseqs, const int* __restrict__ rseqs,
    const int* __restrict__ shc,   const int* __restrict__ shr,
    const float* __restrict__ Mv0)
{
    __shared__ float sw[CT*64];
    __shared__ float sea[CT*64];
    __shared__ int   sq[CT], sx[CT];

    const int bx    = blockIdx.x;
    const int b     = bx >> 3;
    const int c     = (bx >> 1) & 3;
    const int dbase = (bx & 1) * DR;
    const int tid   = threadIdx.x;

    const int g  = tid & 7;
    const int dl = tid >> 3;

    // init mv from Mv0 (pads -> 0)
    unsigned long long mvp[4];
    #pragma unroll
    for (int pi = 0; pi < 4; pi++) {
        int m0 = g + 16*pi, m1 = m0 + 8;
        float v0 = (m0 < MM) ? Mv0[m0*DD + dbase + dl] : 0.f;
        float v1 = (m1 < MM) ? Mv0[m1*DD + dbase + dl] : 0.f;
        PACK2(mvp[pi], v0, v1);
    }
    // compose previous chunks' affine maps
    for (int cc = 0; cc < c; cc++) {
        int bxx = ((b*CC + cc)*2) + (bx & 1);
        #pragma unroll
        for (int pi = 0; pi < 4; pi++) {
            float2 Av = gA[(bxx*4 + pi)*256 + tid];
            float2 Bv = gB[(bxx*4 + pi)*256 + tid];
            unsigned long long Ap, Bp;
            PACK2(Ap, Av.x, Av.y);
            PACK2(Bp, Bv.x, Bv.y);
            FMA2(mvp[pi], Ap, mvp[pi], Bp);   // mv = A*mv + B
        }
    }

    stage_chunk(sw, sea, sq, sx, cseqs, rseqs, shc, shr, b, c, dbase, tid);

    float* outr = g_read + b*LL*DD + (c*CT)*DD + dbase + dl;
    const float fz = 0.f;
    const float2* swp  = (const float2*)sw;
    const float2* seap = (const float2*)sea;

    #pragma unroll 2
    for (int i = 0; i < CT; i++) {
        const float2 ea = seap[i*32 + dl];
        const float ne = -ea.x;
        unsigned long long nep, aap, prp;
        PACK2(nep, ne, ne);
        PACK2(aap, ea.y, ea.y);
        PACK2(prp, fz, fz);

        #pragma unroll
        for (int pi = 0; pi < 4; pi++) {
            float2 w2 = swp[i*32 + pi*8 + g];
            unsigned long long wp, tt;
            PACK2(wp, w2.x, w2.y);
            FMA2(prp, wp, mvp[pi], prp);     // read (before update)
            FMA2(tt, nep, mvp[pi], aap);     // a - e*mv
            FMA2(mvp[pi], wp, tt, mvp[pi]);  // mv += w*(a - e*mv)
        }
        float plo, phi;
        UNPACK2(plo, phi, prp);
        float pr = plo + phi;
        pr += __shfl_xor_sync(0xffffffffu, pr, 1);
        pr += __shfl_xor_sync(0xffffffffu, pr, 2);
        pr += __shfl_xor_sync(0xffffffffu, pr, 4);
        if (g == 0) outr[i*DD] = pr;
    }
}

// ============================================================
// Kernel C: output MLP. 32 positions/block, grid=400, block=256.
// ============================================================
__global__ __launch_bounds__(256) void output_kernel(
    const int*  __restrict__ cseqs, const int* __restrict__ shc,
    const float* __restrict__ Wf,   const float* __restrict__ Wp,
    const float* __restrict__ bp,   float* __restrict__ out)
{
    __shared__ float sW[DD*DD];
    __shared__ float rs[32][DD];

    const int tid   = threadIdx.x;
    const int lane  = tid & 31;
    const int warp  = tid >> 5;
    const int pbase = blockIdx.x * 32;

    #pragma unroll
    for (int j = tid; j < DD*DD/4; j += 256)
        ((float4*)sW)[j] = ((const float4*)Wf)[j];
    #pragma unroll
    for (int j = tid; j < 32*DD/4; j += 256)
        ((float4*)rs)[j] = ((const float4*)(g_read + pbase*DD))[j];
    __syncthreads();

    float acc0[4], acc1[4];
    int posq[4];
    #pragma unroll
    for (int jj = 0; jj < 4; jj++) {
        int pos = pbase + warp*4 + jj;
        int bb = pos / LL, t = pos - bb*LL;
        int q = (t == 0) ? cseqs[bb*L1S] : shc[bb*L1S + t - 1];
        posq[jj] = pos;
        acc0[jj] = g_Kf[q*DD + lane];
        acc1[jj] = g_Kf[q*DD + 32 + lane];
    }

    const float4* r0 = (const float4*)rs[warp*4 + 0];
    const float4* r1 = (const float4*)rs[warp*4 + 1];
    const float4* r2 = (const float4*)rs[warp*4 + 2];
    const float4* r3 = (const float4*)rs[warp*4 + 3];

    #pragma unroll
    for (int i4 = 0; i4 < DD/4; i4++) {
        float ra[4], rb[4], rc[4], rd[4];
        *(float4*)ra = r0[i4];
        *(float4*)rb = r1[i4];
        *(float4*)rc = r2[i4];
        *(float4*)rd = r3[i4];
        #pragma unroll
        for (int k = 0; k < 4; k++) {
            const float wv0 = sW[(4*i4 + k)*DD + lane];
            const float wv1 = sW[(4*i4 + k)*DD + 32 + lane];
            acc0[0] = fmaf(ra[k], wv0, acc0[0]);
            acc1[0] = fmaf(ra[k], wv1, acc1[0]);
            acc0[1] = fmaf(rb[k], wv0, acc0[1]);
            acc1[1] = fmaf(rb[k], wv1, acc1[1]);
            acc0[2] = fmaf(rc[k], wv0, acc0[2]);
            acc1[2] = fmaf(rc[k], wv1, acc1[2]);
            acc0[3] = fmaf(rd[k], wv0, acc0[3]);
            acc1[3] = fmaf(rd[k], wv1, acc1[3]);
        }
    }

    const float wp0 = Wp[lane];
    const float wp1 = Wp[32 + lane];
    const float bpv = bp[0];
    #pragma unroll
    for (int jj = 0; jj < 4; jj++) {
        float p = fast_tanh(acc0[jj]) * wp0 + fast_tanh(acc1[jj]) * wp1;
        #pragma unroll
        for (int o = 16; o > 0; o >>= 1)
            p += __shfl_xor_sync(0xffffffffu, p, o);
        if (lane == 0)
            out[posq[jj]] = fast_sigmoid(p + bpv);
    }
}

// ============================================================
extern "C" void kernel_launch(void* const* d_in, const int* in_sizes, int n_in,
                              void* d_out, int out_size)
{
    const int*   cseqs = (const int*)  d_in[0];
    const int*   rseqs = (const int*)  d_in[1];
    const int*   shc   = (const int*)  d_in[2];
    const int*   shr   = (const int*)  d_in[3];
    const float* kemb  = (const float*)d_in[4];
    const float* vemb  = (const float*)d_in[5];
    const float* Mk    = (const float*)d_in[6];
    const float* Mv0   = (const float*)d_in[7];
    const float* Wf    = (const float*)d_in[8];
    const float* bf    = (const float*)d_in[9];
    const float* We    = (const float*)d_in[10];
    const float* be    = (const float*)d_in[11];
    const float* Wa    = (const float*)d_in[12];
    const float* ba    = (const float*)d_in[13];
    const float* Wp    = (const float*)d_in[14];
    const float* bp    = (const float*)d_in[15];
    float* out = (float*)d_out;

    size_t vsm = (size_t)(2*DD*DD + 8*DD + 32) * sizeof(float);
    cudaFuncSetAttribute(vocab_kernel,
                         cudaFuncAttributeMaxDynamicSharedMemorySize, (int)vsm);
    vocab_kernel<<<NEA + NWK, 256, vsm>>>(kemb, vemb, Mk, We, be, Wa, ba, Wf, bf);

    scan_phase1<<<NBLK, 256>>>(cseqs, rseqs, shc, shr);
    scan_phase3<<<NBLK, 256>>>(cseqs, rseqs, shc, shr, Mv0);

    output_kernel<<<BB*LL/32, 256>>>(cseqs, shc, Wf, Wp, bp, out);
}

// round 8
// speedup vs baseline: 1.1009x; 1.0074x over previous
#include <cuda_runtime.h>

#define BB    64
#define L1S   199
#define LL    200
#define NUMC  1000
#define DD    64
#define MM    50
#define DR    32          // d-range per scan block (d-split = 2)
#define CC    4           // time chunks
#define CT    50          // steps per chunk (LL/CC)
#define NBLK  (BB*CC*2)   // 512 phase blocks

// ---- scratch (static device globals; no allocation) ----
__device__ float  g_Wall[NUMC*64];     // softmax, padded to 64 (zeros 50..63)
__device__ float  g_Eall[2*NUMC*DD];   // sigmoid(vemb @ We + be)
__device__ float  g_Aall[2*NUMC*DD];   // tanh(vemb @ Wa + ba)
__device__ float  g_Kf  [NUMC*DD];     // kemb @ Wf[D:2D] + bf
__device__ float  g_read[BB*LL*DD];    // weighted read
__device__ float2 gA[NBLK*4*256];      // chunk affine scale  (per pair,thread)
__device__ float2 gB[NBLK*4*256];      // chunk affine offset

// ---- fast transcendentals ----
__device__ __forceinline__ float fast_sigmoid(float x) {
    return __fdividef(1.f, 1.f + __expf(-x));
}
__device__ __forceinline__ float fast_tanh(float x) {
    return 1.f - __fdividef(2.f, __expf(2.f * x) + 1.f);
}

// ---- packed f32x2 ops ----
#define FMA2(d, a, b, c) \
    asm("fma.rn.f32x2 %0, %1, %2, %3;" : "=l"(d) : "l"(a), "l"(b), "l"(c))
#define MUL2(d, a, b) \
    asm("mul.rn.f32x2 %0, %1, %2;" : "=l"(d) : "l"(a), "l"(b))
#define PACK2(d, lo, hi) \
    asm("mov.b64 %0, {%1, %2};" : "=l"(d) : "f"(lo), "f"(hi))
#define UNPACK2(lo, hi, s) \
    asm("mov.b64 {%0, %1}, %2;" : "=f"(lo), "=f"(hi) : "l"(s))

#define NEA 250
#define NWK 125

// ============================================================
// Kernel V: role-split vocab precompute (float4 staging).
// ============================================================
__global__ __launch_bounds__(256) void vocab_kernel(
    const float* __restrict__ kemb,  const float* __restrict__ vemb,
    const float* __restrict__ Mk,
    const float* __restrict__ We,    const float* __restrict__ be,
    const float* __restrict__ Wa,    const float* __restrict__ ba,
    const float* __restrict__ Wf,    const float* __restrict__ bf)
{
    extern __shared__ float sm[];
    const int tid = threadIdx.x;
    const int d   = tid & 63;
    const int pg  = tid >> 6;

    if (blockIdx.x < NEA) {
        float* sWe = sm;
        float* sWa = sWe + DD*DD;
        float* vs  = sWa + DD*DD;
        const int xbase = blockIdx.x * 8;

        #pragma unroll
        for (int j = tid; j < DD*DD/4; j += 256) {
            ((float4*)sWe)[j] = ((const float4*)We)[j];
            ((float4*)sWa)[j] = ((const float4*)Wa)[j];
        }
        #pragma unroll
        for (int j = tid; j < 8*DD/4; j += 256)
            ((float4*)vs)[j] = ((const float4*)(vemb + xbase*DD))[j];
        __syncthreads();

        const float bev = be[d], bav = ba[d];
        float ed0 = bev, ed1 = bev, ad0 = bav, ad1 = bav;
        const float* v0 = vs + (pg*2 + 0)*DD;
        const float* v1 = vs + (pg*2 + 1)*DD;
        #pragma unroll 8
        for (int i = 0; i < DD; i++) {
            const float we = sWe[i*DD + d];
            const float wa = sWa[i*DD + d];
            const float a0 = v0[i], a1 = v1[i];
            ed0 = fmaf(a0, we, ed0);  ad0 = fmaf(a0, wa, ad0);
            ed1 = fmaf(a1, we, ed1);  ad1 = fmaf(a1, wa, ad1);
        }
        int r0 = xbase + pg*2, r1 = r0 + 1;
        g_Eall[r0*DD + d] = fast_sigmoid(ed0);
        g_Aall[r0*DD + d] = fast_tanh(ad0);
        g_Eall[r1*DD + d] = fast_sigmoid(ed1);
        g_Aall[r1*DD + d] = fast_tanh(ad1);
    } else {
        float* sWf  = sm;
        float* sMkT = sWf + DD*DD;
        float* ks   = sMkT + DD*MM;
        float* part = ks + 8*DD;
        const int kbase = (blockIdx.x - NEA) * 8;

        #pragma unroll
        for (int j = tid; j < DD*DD/4; j += 256)
            ((float4*)sWf)[j] = ((const float4*)(Wf + DD*DD))[j];
        #pragma unroll
        for (int j = tid; j < MM*DD; j += 256) {
            int m = j >> 6, i = j & 63;
            sMkT[i*MM + m] = Mk[j];
        }
        #pragma unroll
        for (int j = tid; j < 8*DD/4; j += 256)
            ((float4*)ks)[j] = ((const float4*)(kemb + kbase*DD))[j];
        __syncthreads();

        const float bfv = bf[d];
        float kf0 = bfv, kf1 = bfv;
        float lg0 = 0.f, lg1 = 0.f;
        const int md = (d < MM) ? d : 0;
        const float* k0 = ks + (pg*2 + 0)*DD;
        const float* k1 = ks + (pg*2 + 1)*DD;
        #pragma unroll 8
        for (int i = 0; i < DD; i++) {
            const float wf = sWf[i*DD + d];
            const float mk = sMkT[i*MM + md];
            const float a0 = k0[i], a1 = k1[i];
            kf0 = fmaf(a0, wf, kf0);  lg0 = fmaf(a0, mk, lg0);
            kf1 = fmaf(a1, wf, kf1);  lg1 = fmaf(a1, mk, lg1);
        }
        g_Kf[(kbase + pg*2 + 0)*DD + d] = kf0;
        g_Kf[(kbase + pg*2 + 1)*DD + d] = kf1;

        float lgv0 = (d < MM) ? __expf(lg0) : 0.f;
        float lgv1 = (d < MM) ? __expf(lg1) : 0.f;
        float ps0 = lgv0, ps1 = lgv1;
        #pragma unroll
        for (int o = 16; o > 0; o >>= 1) {
            ps0 += __shfl_xor_sync(0xffffffffu, ps0, o);
            ps1 += __shfl_xor_sync(0xffffffffu, ps1, o);
        }
        if ((d & 31) == 0) {
            part[pg*4 + (d >> 5)]     = ps0;
            part[pg*4 + 2 + (d >> 5)] = ps1;
        }
        __syncthreads();
        // padded rows (stride 64): zeros for d >= 50
        g_Wall[(kbase + pg*2 + 0)*64 + d] =
            __fdividef(lgv0, part[pg*4] + part[pg*4 + 1]);
        g_Wall[(kbase + pg*2 + 1)*64 + d] =
            __fdividef(lgv1, part[pg*4 + 2] + part[pg*4 + 3]);
    }
}

// ---- shared staging helper for phase kernels (inlined) ----
// sw: CT*64 permuted padded w; sea: CT*64 interleaved (e,a) for DR d-lanes
__device__ __forceinline__ void stage_chunk(
    float* sw, float* sea, int* sq, int* sx,
    const int* cseqs, const int* rseqs, const int* shc, const int* shr,
    int b, int c, int dbase, int tid)
{
    if (tid < CT) {
        int t = c*CT + tid;
        int q  = (t == 0) ? cseqs[b*L1S] : shc[b*L1S + t - 1];
        int rr = (t == 0) ? rseqs[b*L1S] : shr[b*L1S + t - 1];
        sq[tid] = q;
        sx[tid] = q + NUMC * rr;
    }
    __syncthreads();

    // w: CT rows x 16 float4 (stride-64 padded rows), permuted scatter
    for (int j = tid; j < CT*16; j += 256) {
        int i = j >> 4, f4 = j & 15;
        float4 wv = *(const float4*)&g_Wall[sq[i]*64 + f4*4];
        const float* w = (const float*)&wv;
        #pragma unroll
        for (int k = 0; k < 4; k++) {
            int m = f4*4 + k;
            int idx = (m >> 4)*16 + ((m & 7) << 1) + ((m >> 3) & 1);
            sw[i*64 + idx] = w[k];
        }
    }
    // (e,a): CT rows x 8 float4 over the DR d-lanes, interleaved
    for (int j = tid; j < CT*8; j += 256) {
        int i = j >> 3, f4 = j & 7;
        int off = sx[i]*DD + dbase + f4*4;
        float4 ev = *(const float4*)&g_Eall[off];
        float4 av = *(const float4*)&g_Aall[off];
        const float* e = (const float*)&ev;
        const float* a = (const float*)&av;
        #pragma unroll
        for (int k = 0; k < 4; k++) {
            sea[i*64 + (f4*4 + k)*2 + 0] = e[k];
            sea[i*64 + (f4*4 + k)*2 + 1] = a[k];
        }
    }
    __syncthreads();
}

// ============================================================
// Phase 1: per-chunk affine composition (A,B). grid = 512.
// block = (b*CC + c)*2 + half, 256 threads (g=tid&7, dl=tid>>3).
// ============================================================
__global__ __launch_bounds__(256) void scan_phase1(
    const int* __restrict__ cseqs, const int* __restrict__ rseqs,
    const int* __restrict__ shc,   const int* __restrict__ shr)
{
    __shared__ float sw[CT*64];
    __shared__ float sea[CT*64];
    __shared__ int   sq[CT], sx[CT];

    const int bx    = blockIdx.x;
    const int b     = bx >> 3;
    const int c     = (bx >> 1) & 3;
    const int dbase = (bx & 1) * DR;
    const int tid   = threadIdx.x;

    stage_chunk(sw, sea, sq, sx, cseqs, rseqs, shc, shr, b, c, dbase, tid);

    const int g  = tid & 7;
    const int dl = tid >> 3;
    (void)g; (void)dl;

    const float f1 = 1.f, f0 = 0.f;
    unsigned long long onep, A[4], Bv[4];
    PACK2(onep, f1, f1);
    #pragma unroll
    for (int pi = 0; pi < 4; pi++) { A[pi] = onep; PACK2(Bv[pi], f0, f0); }

    const float2* swp  = (const float2*)sw;
    const float2* seap = (const float2*)sea;

    #pragma unroll 2
    for (int i = 0; i < CT; i++) {
        const float2 ea = seap[i*32 + (tid >> 3)];
        const float ne = -ea.x;
        unsigned long long nep, ap;
        PACK2(nep, ne, ne);
        PACK2(ap, ea.y, ea.y);
        #pragma unroll
        for (int pi = 0; pi < 4; pi++) {
            float2 w2 = swp[i*32 + pi*8 + (tid & 7)];
            unsigned long long wp, alpha, beta;
            PACK2(wp, w2.x, w2.y);
            FMA2(alpha, nep, wp, onep);      // alpha = 1 - e*w
            MUL2(beta, wp, ap);              // beta  = w*a
            MUL2(A[pi], A[pi], alpha);       // A *= alpha
            FMA2(Bv[pi], alpha, Bv[pi], beta); // B = alpha*B + beta
        }
    }

    #pragma unroll
    for (int pi = 0; pi < 4; pi++) {
        float lo, hi;
        UNPACK2(lo, hi, A[pi]);
        gA[(bx*4 + pi)*256 + tid] = make_float2(lo, hi);
        UNPACK2(lo, hi, Bv[pi]);
        gB[(bx*4 + pi)*256 + tid] = make_float2(lo, hi);
    }
}

// ============================================================
// Phase 3: compose chunk-start state, replay 50 steps, emit reads.
// grid = 512, 256 threads.
// ============================================================
__global__ __launch_bounds__(256) void scan_phase3(
    const int* __restrict__ cseqs, const int* __restrict__ rseqs,
    const int* __restrict__ shc,   const int* __restrict__ shr,
    const float* __restrict__ Mv0)
{
    __shared__ float sw[CT*64];
    __shared__ float sea[CT*64];
    __shared__ int   sq[CT], sx[CT];

    const int bx    = blockIdx.x;
    const int b     = bx >> 3;
    const int c     = (bx >> 1) & 3;
    const int dbase = (bx & 1) * DR;
    const int tid   = threadIdx.x;

    const int g  = tid & 7;
    const int dl = tid >> 3;

    // init mv from Mv0 (pads -> 0)
    unsigned long long mvp[4];
    #pragma unroll
    for (int pi = 0; pi < 4; pi++) {
        int m0 = g + 16*pi, m1 = m0 + 8;
        float v0 = (m0 < MM) ? Mv0[m0*DD + dbase + dl] : 0.f;
        float v1 = (m1 < MM) ? Mv0[m1*DD + dbase + dl] : 0.f;
        PACK2(mvp[pi], v0, v1);
    }
    // compose previous chunks' affine maps
    for (int cc = 0; cc < c; cc++) {
        int bxx = ((b*CC + cc)*2) + (bx & 1);
        #pragma unroll
        for (int pi = 0; pi < 4; pi++) {
            float2 Av = gA[(bxx*4 + pi)*256 + tid];
            float2 Bv = gB[(bxx*4 + pi)*256 + tid];
            unsigned long long Ap, Bp;
            PACK2(Ap, Av.x, Av.y);
            PACK2(Bp, Bv.x, Bv.y);
            FMA2(mvp[pi], Ap, mvp[pi], Bp);   // mv = A*mv + B
        }
    }

    stage_chunk(sw, sea, sq, sx, cseqs, rseqs, shc, shr, b, c, dbase, tid);

    float* outr = g_read + b*LL*DD + (c*CT)*DD + dbase + dl;
    const float fz = 0.f;
    const float2* swp  = (const float2*)sw;
    const float2* seap = (const float2*)sea;

    #pragma unroll 2
    for (int i = 0; i < CT; i++) {
        const float2 ea = seap[i*32 + dl];
        const float ne = -ea.x;
        unsigned long long nep, aap, prp;
        PACK2(nep, ne, ne);
        PACK2(aap, ea.y, ea.y);
        PACK2(prp, fz, fz);

        #pragma unroll
        for (int pi = 0; pi < 4; pi++) {
            float2 w2 = swp[i*32 + pi*8 + g];
            unsigned long long wp, tt;
            PACK2(wp, w2.x, w2.y);
            FMA2(prp, wp, mvp[pi], prp);     // read (before update)
            FMA2(tt, nep, mvp[pi], aap);     // a - e*mv
            FMA2(mvp[pi], wp, tt, mvp[pi]);  // mv += w*(a - e*mv)
        }
        float plo, phi;
        UNPACK2(plo, phi, prp);
        float pr = plo + phi;
        pr += __shfl_xor_sync(0xffffffffu, pr, 1);
        pr += __shfl_xor_sync(0xffffffffu, pr, 2);
        pr += __shfl_xor_sync(0xffffffffu, pr, 4);
        if (g == 0) outr[i*DD] = pr;
    }
}

// ============================================================
// Kernel C: output MLP. 32 positions/block, grid=400, block=256.
// ============================================================
__global__ __launch_bounds__(256) void output_kernel(
    const int*  __restrict__ cseqs, const int* __restrict__ shc,
    const float* __restrict__ Wf,   const float* __restrict__ Wp,
    const float* __restrict__ bp,   float* __restrict__ out)
{
    __shared__ float sW[DD*DD];
    __shared__ float rs[32][DD];

    const int tid   = threadIdx.x;
    const int lane  = tid & 31;
    const int warp  = tid >> 5;
    const int pbase = blockIdx.x * 32;

    #pragma unroll
    for (int j = tid; j < DD*DD/4; j += 256)
        ((float4*)sW)[j] = ((const float4*)Wf)[j];
    #pragma unroll
    for (int j = tid; j < 32*DD/4; j += 256)
        ((float4*)rs)[j] = ((const float4*)(g_read + pbase*DD))[j];
    __syncthreads();

    float acc0[4], acc1[4];
    int posq[4];
    #pragma unroll
    for (int jj = 0; jj < 4; jj++) {
        int pos = pbase + warp*4 + jj;
        int bb = pos / LL, t = pos - bb*LL;
        int q = (t == 0) ? cseqs[bb*L1S] : shc[bb*L1S + t - 1];
        posq[jj] = pos;
        acc0[jj] = g_Kf[q*DD + lane];
        acc1[jj] = g_Kf[q*DD + 32 + lane];
    }

    const float4* r0 = (const float4*)rs[warp*4 + 0];
    const float4* r1 = (const float4*)rs[warp*4 + 1];
    const float4* r2 = (const float4*)rs[warp*4 + 2];
    const float4* r3 = (const float4*)rs[warp*4 + 3];

    #pragma unroll
    for (int i4 = 0; i4 < DD/4; i4++) {
        float ra[4], rb[4], rc[4], rd[4];
        *(float4*)ra = r0[i4];
        *(float4*)rb = r1[i4];
        *(float4*)rc = r2[i4];
        *(float4*)rd = r3[i4];
        #pragma unroll
        for (int k = 0; k < 4; k++) {
            const float wv0 = sW[(4*i4 + k)*DD + lane];
            const float wv1 = sW[(4*i4 + k)*DD + 32 + lane];
            acc0[0] = fmaf(ra[k], wv0, acc0[0]);
            acc1[0] = fmaf(ra[k], wv1, acc1[0]);
            acc0[1] = fmaf(rb[k], wv0, acc0[1]);
            acc1[1] = fmaf(rb[k], wv1, acc1[1]);
            acc0[2] = fmaf(rc[k], wv0, acc0[2]);
            acc1[2] = fmaf(rc[k], wv1, acc1[2]);
            acc0[3] = fmaf(rd[k], wv0, acc0[3]);
            acc1[3] = fmaf(rd[k], wv1, acc1[3]);
        }
    }

    const float wp0 = Wp[lane];
    const float wp1 = Wp[32 + lane];
    const float bpv = bp[0];
    #pragma unroll
    for (int jj = 0; jj < 4; jj++) {
        float p = fast_tanh(acc0[jj]) * wp0 + fast_tanh(acc1[jj]) * wp1;
        #pragma unroll
        for (int o = 16; o > 0; o >>= 1)
            p += __shfl_xor_sync(0xffffffffu, p, o);
        if (lane == 0)
            out[posq[jj]] = fast_sigmoid(p + bpv);
    }
}

// ============================================================
extern "C" void kernel_launch(void* const* d_in, const int* in_sizes, int n_in,
                              void* d_out, int out_size)
{
    const int*   cseqs = (const int*)  d_in[0];
    const int*   rseqs = (const int*)  d_in[1];
    const int*   shc   = (const int*)  d_in[2];
    const int*   shr   = (const int*)  d_in[3];
    const float* kemb  = (const float*)d_in[4];
    const float* vemb  = (const float*)d_in[5];
    const float* Mk    = (const float*)d_in[6];
    const float* Mv0   = (const float*)d_in[7];
    const float* Wf    = (const float*)d_in[8];
    const float* bf    = (const float*)d_in[9];
    const float* We    = (const float*)d_in[10];
    const float* be    = (const float*)d_in[11];
    const float* Wa    = (const float*)d_in[12];
    const float* ba    = (const float*)d_in[13];
    const float* Wp    = (const float*)d_in[14];
    const float* bp    = (const float*)d_in[15];
    float* out = (float*)d_out;

    size_t vsm = (size_t)(2*DD*DD + 8*DD + 32) * sizeof(float);
    cudaFuncSetAttribute(vocab_kernel,
                         cudaFuncAttributeMaxDynamicSharedMemorySize, (int)vsm);
    vocab_kernel<<<NEA + NWK, 256, vsm>>>(kemb, vemb, Mk, We, be, Wa, ba, Wf, bf);

    scan_phase1<<<NBLK, 256>>>(cseqs, rseqs, shc, shr);
    scan_phase3<<<NBLK, 256>>>(cseqs, rseqs, shc, shr, Mv0);

    output_kernel<<<BB*LL/32, 256>>>(cseqs, shc, Wf, Wp, bp, out);
}